// round 10
// baseline (speedup 1.0000x reference)
#include <cuda_runtime.h>
#include <math.h>
#include <float.h>
#include <stdint.h>

#define N_SAMPLES 8192
#define DIM 128
#define NCLUST 64
#define TILE 128
#define NTILES (N_SAMPLES / TILE)   // 64
#define NPAIRS (NTILES * (NTILES + 1) / 2)   // 2080
#define KS 16                       // k-slab size
#define NSLAB (DIM / KS)            // 8
#define SPAD 65

// smem offsets in floats (slab buffer = KS*TILE = 2048 floats = 8KB)
#define AS0 0
#define AS1 2048
#define BS0 4096
#define BS1 6144
#define SACCI 8192
#define SACCJ (SACCI + TILE * SPAD)
#define SMEM_FLOATS (SACCJ + TILE * SPAD)   // 24832 floats = 97KB

// ---- device scratch ----
__device__ int   g_lab[N_SAMPLES];
__device__ int   g_labS[N_SAMPLES];
__device__ int   g_perm[N_SAMPLES];
__device__ float g_sqS[N_SAMPLES];
__device__ float g_FpT[DIM * N_SAMPLES];    // sorted, k-major
__device__ int   g_counts[NCLUST];
// [partner_tile][cluster][row] -- each slot written by exactly one CTA
__device__ float g_Spart[NTILES * NCLUST * N_SAMPLES];
__device__ float g_partial[32];

typedef unsigned long long ull;

__device__ __forceinline__ void fma2(ull& acc, ull a, ull b) {
    asm("fma.rn.f32x2 %0, %1, %2, %0;" : "+l"(acc) : "l"(a), "l"(b));
}
__device__ __forceinline__ ull dup2(float a) {
    ull r;
    asm("mov.b64 %0, {%1, %1};" : "=l"(r) : "f"(a));
    return r;
}
__device__ __forceinline__ uint32_t smem_u32(const void* p) {
    uint32_t a;
    asm("{ .reg .u64 t; cvta.to.shared.u64 t, %1; cvt.u32.u64 %0, t; }"
        : "=r"(a) : "l"(p));
    return a;
}
__device__ __forceinline__ void cp16(uint32_t dst, const void* src) {
    asm volatile("cp.async.cg.shared.global [%0], [%1], 16;"
                 :: "r"(dst), "l"(src) : "memory");
}
#define CP_COMMIT() asm volatile("cp.async.commit_group;" ::: "memory")
#define CP_WAIT1()  asm volatile("cp.async.wait_group 1;" ::: "memory")
#define CP_WAIT0()  asm volatile("cp.async.wait_group 0;" ::: "memory")

// ---------------------------------------------------------------------------
__global__ void conv_labels_kernel(const int* __restrict__ Lraw) {
    __shared__ int is64;
    if (threadIdx.x == 0) {
        int odd_or = 0, even_bad = 0;
        for (int k = 0; k < 256; k += 2) {
            odd_or   |= Lraw[k + 1];
            even_bad |= ((unsigned)Lraw[k] >= NCLUST);
        }
        is64 = (odd_or == 0 && !even_bad) ? 1 : 0;
    }
    __syncthreads();
    const int w = is64;
    for (int i = threadIdx.x; i < N_SAMPLES; i += blockDim.x) {
        int v = w ? Lraw[2 * i] : Lraw[i];
        g_lab[i] = min(max(v, 0), NCLUST - 1);
    }
}

// Deterministic counting sort by label: 256 segments x 32 elements.
__global__ void sort_kernel() {
    __shared__ unsigned short T[256][NCLUST];
    __shared__ int colTot[NCLUST];
    __shared__ int cbase[NCLUST];
    const int s = threadIdx.x;
#pragma unroll
    for (int c = 0; c < NCLUST; c++) T[s][c] = 0;
    const int e0 = s * 32;
    for (int e = 0; e < 32; e++) T[s][g_lab[e0 + e]]++;
    __syncthreads();
    if (s < NCLUST) {
        int tot = 0;
        for (int q = 0; q < 256; q++) tot += T[q][s];
        colTot[s] = tot;
        g_counts[s] = tot;
    }
    __syncthreads();
    if (s == 0) {
        int run = 0;
        for (int c = 0; c < NCLUST; c++) { cbase[c] = run; run += colTot[c]; }
    }
    __syncthreads();
    if (s < NCLUST) {
        int run = cbase[s];
        for (int q = 0; q < 256; q++) {
            int w = T[q][s];
            T[q][s] = (unsigned short)run;
            run += w;
        }
    }
    __syncthreads();
    for (int e = 0; e < 32; e++) {
        int idx = e0 + e;
        int c = g_lab[idx];
        int p = T[s][c]++;
        g_perm[p] = idx;
        g_labS[p] = c;
    }
}

// Gather (via perm) + transpose to k-major + sq norms, fused.
// Block: 32 sorted rows. Scalar STS (row stride 129 is only 4B-aligned).
__global__ void gatherT_kernel(const float* __restrict__ F) {
    __shared__ float T[32][DIM + 1];
    const int tid = threadIdx.x;
    const int lane = tid & 31, w = tid >> 5;
    const int base = blockIdx.x * 32;

#pragma unroll
    for (int rr = 0; rr < 4; rr++) {
        const int p = base + w * 4 + rr;
        const int src = g_perm[p];
        float4 v = reinterpret_cast<const float4*>(F)[src * 32 + lane];
        T[w * 4 + rr][lane * 4 + 0] = v.x;
        T[w * 4 + rr][lane * 4 + 1] = v.y;
        T[w * 4 + rr][lane * 4 + 2] = v.z;
        T[w * 4 + rr][lane * 4 + 3] = v.w;
        float s = v.x * v.x + v.y * v.y + v.z * v.z + v.w * v.w;
#pragma unroll
        for (int o = 16; o > 0; o >>= 1) s += __shfl_down_sync(0xffffffffu, s, o);
        if (lane == 0) g_sqS[p] = s;
    }
    __syncthreads();

    const int i = tid & 31, ksub = tid >> 5;
#pragma unroll
    for (int step = 0; step < 16; step++) {
        int k = step * 8 + ksub;
        g_FpT[(size_t)k * N_SAMPLES + base + i] = T[i][k];
    }
}

// ---------------------------------------------------------------------------
// dist: one 128x128 tile per CTA, linear triangular grid (jt >= it).
// 8x8 reg tiling, FFMA2, cp.async double-buffered slabs, manual k+1 prefetch.
__global__ __launch_bounds__(256, 2) void dist_kernel() {
    // decode triangular pair
    int it = 0, rem = blockIdx.x, cnt = NTILES;
    while (rem >= cnt) { rem -= cnt; cnt--; it++; }
    const int jt = it + rem;
    const bool diag = (it == jt);

    extern __shared__ __align__(16) float smem[];
    const uint32_t sb = smem_u32(smem);
    const int tid = threadIdx.x;
    const int tx = tid & 15, ty = tid >> 4;
    const int iBase = it * TILE;
    const int jBase = jt * TILE;

    for (int t = tid; t < 2 * TILE * SPAD; t += 256) smem[SACCI + t] = 0.f;

#define ISSUE_SLAB(u)                                                         \
    {                                                                         \
        const int _b = (u) & 1;                                               \
        const float* srcA = g_FpT + (size_t)((u) * KS) * N_SAMPLES + iBase;   \
        const float* srcB = g_FpT + (size_t)((u) * KS) * N_SAMPLES + jBase;   \
        const uint32_t dA = sb + (_b ? AS1 : AS0) * 4;                        \
        const uint32_t dB = sb + (_b ? BS1 : BS0) * 4;                        \
        _Pragma("unroll")                                                     \
        for (int rr = 0; rr < 2; rr++) {                                      \
            int c = tid + rr * 256;                                           \
            int kk = c >> 5, off = (c & 31) * 4;                              \
            cp16(dA + (uint32_t)(kk * TILE + off) * 4,                        \
                 srcA + (size_t)kk * N_SAMPLES + off);                        \
            cp16(dB + (uint32_t)(kk * TILE + off) * 4,                        \
                 srcB + (size_t)kk * N_SAMPLES + off);                        \
        }                                                                     \
        CP_COMMIT();                                                          \
    }

    float isq[8];
#pragma unroll
    for (int ii = 0; ii < 8; ii++) isq[ii] = g_sqS[iBase + ty * 8 + ii];

    ull acc[32];
#pragma unroll
    for (int z = 0; z < 32; z++) acc[z] = 0ull;

    ISSUE_SLAB(0);
    ISSUE_SLAB(1);
    CP_WAIT1();
    __syncthreads();

#pragma unroll 1
    for (int u = 0; u < NSLAB; u++) {
        const int p = u & 1;
        const float* Ab = smem + (p ? AS1 : AS0) + ty * 8;
        const float* bp = smem + (p ? BS1 : BS0) + tx * 8;

        // software pipeline: preload k=0, then per k: prefetch k+1, compute k
        float4 aLoC = *reinterpret_cast<const float4*>(Ab);
        float4 aHiC = *reinterpret_cast<const float4*>(Ab + 4);
        ull b0C, b1C, b2C, b3C;
        asm("ld.shared.v2.u64 {%0, %1}, [%2];" : "=l"(b0C), "=l"(b1C) : "l"(bp));
        asm("ld.shared.v2.u64 {%0, %1}, [%2];" : "=l"(b2C), "=l"(b3C) : "l"(bp + 4));

#pragma unroll
        for (int k = 0; k < KS; k++) {
            float4 aLoN, aHiN;
            ull b0N, b1N, b2N, b3N;
            if (k + 1 < KS) {
                aLoN = *reinterpret_cast<const float4*>(Ab + (k + 1) * TILE);
                aHiN = *reinterpret_cast<const float4*>(Ab + (k + 1) * TILE + 4);
                asm("ld.shared.v2.u64 {%0, %1}, [%2];"
                    : "=l"(b0N), "=l"(b1N) : "l"(bp + (k + 1) * TILE));
                asm("ld.shared.v2.u64 {%0, %1}, [%2];"
                    : "=l"(b2N), "=l"(b3N) : "l"(bp + (k + 1) * TILE + 4));
            }
            ull a;
            a = dup2(aLoC.x); fma2(acc[0],  a, b0C); fma2(acc[1],  a, b1C); fma2(acc[2],  a, b2C); fma2(acc[3],  a, b3C);
            a = dup2(aLoC.y); fma2(acc[4],  a, b0C); fma2(acc[5],  a, b1C); fma2(acc[6],  a, b2C); fma2(acc[7],  a, b3C);
            a = dup2(aLoC.z); fma2(acc[8],  a, b0C); fma2(acc[9],  a, b1C); fma2(acc[10], a, b2C); fma2(acc[11], a, b3C);
            a = dup2(aLoC.w); fma2(acc[12], a, b0C); fma2(acc[13], a, b1C); fma2(acc[14], a, b2C); fma2(acc[15], a, b3C);
            a = dup2(aHiC.x); fma2(acc[16], a, b0C); fma2(acc[17], a, b1C); fma2(acc[18], a, b2C); fma2(acc[19], a, b3C);
            a = dup2(aHiC.y); fma2(acc[20], a, b0C); fma2(acc[21], a, b1C); fma2(acc[22], a, b2C); fma2(acc[23], a, b3C);
            a = dup2(aHiC.z); fma2(acc[24], a, b0C); fma2(acc[25], a, b1C); fma2(acc[26], a, b2C); fma2(acc[27], a, b3C);
            a = dup2(aHiC.w); fma2(acc[28], a, b0C); fma2(acc[29], a, b1C); fma2(acc[30], a, b2C); fma2(acc[31], a, b3C);
            aLoC = aLoN; aHiC = aHiN;
            b0C = b0N; b1C = b1N; b2C = b2N; b3C = b3N;
        }
        __syncthreads();
        if (u + 2 < NSLAB) {
            ISSUE_SLAB(u + 2);
            CP_WAIT1();
        } else {
            CP_WAIT0();
        }
        __syncthreads();
    }
#undef ISSUE_SLAB

    // ---- epilogue ----
    const int jbase = tx * 8;
    int   jlr[8], ilr[8];
    float jsr[8];
#pragma unroll
    for (int jj = 0; jj < 8; jj++) {
        jlr[jj] = g_labS[jBase + jbase + jj];
        jsr[jj] = g_sqS[jBase + jbase + jj];
        ilr[jj] = g_labS[iBase + ty * 8 + jj];
    }

#pragma unroll
    for (int q = 0; q < 32; q++) {
        const int ii = q >> 2, jp = q & 3;
        ull a2 = acc[q];
        float lo = __uint_as_float((unsigned)(a2 & 0xffffffffull));
        float hi = __uint_as_float((unsigned)(a2 >> 32));
        float d2lo = isq[ii] + jsr[2 * jp]     - 2.f * lo;
        float d2hi = isq[ii] + jsr[2 * jp + 1] - 2.f * hi;
        float dlo = 0.f, dhi = 0.f;
        const int gi = iBase + ty * 8 + ii;
        if (d2lo > 0.f && gi != (jBase + jbase + 2 * jp))
            asm("sqrt.approx.f32 %0, %1;" : "=f"(dlo) : "f"(d2lo));
        if (d2hi > 0.f && gi != (jBase + jbase + 2 * jp + 1))
            asm("sqrt.approx.f32 %0, %1;" : "=f"(dhi) : "f"(d2hi));
        asm("mov.b64 %0, {%1, %2};" : "=l"(acc[q]) : "f"(dlo), "f"(dhi));
    }

    float* SaccI = smem + SACCI;
    float* SaccJ = smem + SACCJ;

    // i-side: run-length over sorted j-labels
    {
        float run[8];
#pragma unroll
        for (int ii = 0; ii < 8; ii++) run[ii] = 0.f;
        int cur = jlr[0];
#pragma unroll
        for (int jj = 0; jj < 8; jj++) {
            const int c = jlr[jj];
            if (c != cur) {
#pragma unroll
                for (int ii = 0; ii < 8; ii++) {
                    atomicAdd(&SaccI[(ty * 8 + ii) * SPAD + cur], run[ii]);
                    run[ii] = 0.f;
                }
                cur = c;
            }
            const int jp = jj >> 1;
#pragma unroll
            for (int ii = 0; ii < 8; ii++) {
                ull a2 = acc[ii * 4 + jp];
                float d = (jj & 1) ? __uint_as_float((unsigned)(a2 >> 32))
                                   : __uint_as_float((unsigned)(a2 & 0xffffffffull));
                run[ii] += d;
            }
        }
#pragma unroll
        for (int ii = 0; ii < 8; ii++)
            atomicAdd(&SaccI[(ty * 8 + ii) * SPAD + cur], run[ii]);
    }

    // j-side (off-diag only): run-length over sorted i-labels
    if (!diag) {
        float run[8];
#pragma unroll
        for (int jj = 0; jj < 8; jj++) run[jj] = 0.f;
        int cur = ilr[0];
#pragma unroll
        for (int ii = 0; ii < 8; ii++) {
            const int c = ilr[ii];
            if (c != cur) {
#pragma unroll
                for (int jj = 0; jj < 8; jj++) {
                    atomicAdd(&SaccJ[(jbase + jj) * SPAD + cur], run[jj]);
                    run[jj] = 0.f;
                }
                cur = c;
            }
#pragma unroll
            for (int jj = 0; jj < 8; jj++) {
                ull a2 = acc[ii * 4 + (jj >> 1)];
                float d = (jj & 1) ? __uint_as_float((unsigned)(a2 >> 32))
                                   : __uint_as_float((unsigned)(a2 & 0xffffffffull));
                run[jj] += d;
            }
        }
#pragma unroll
        for (int jj = 0; jj < 8; jj++)
            atomicAdd(&SaccJ[(jbase + jj) * SPAD + cur], run[jj]);
    }
    __syncthreads();

    for (int idx = tid; idx < TILE * NCLUST; idx += 256) {
        int c = idx >> 7, il = idx & 127;
        g_Spart[(size_t)(jt * NCLUST + c) * N_SAMPLES + iBase + il] =
            SaccI[il * SPAD + c];
    }
    if (!diag) {
        for (int idx = tid; idx < TILE * NCLUST; idx += 256) {
            int c = idx >> 7, il = idx & 127;
            g_Spart[(size_t)(it * NCLUST + c) * N_SAMPLES + jBase + il] =
                SaccJ[il * SPAD + c];
        }
    }
}

// ---------------------------------------------------------------------------
// score: fused partner-reduction + silhouette + block partial sums.
__global__ void score_kernel() {
    const int i = blockIdx.x * 256 + threadIdx.x;
    __shared__ int scounts[NCLUST];
    if (threadIdx.x < NCLUST) scounts[threadIdx.x] = g_counts[threadIdx.x];
    __syncthreads();

    const int own = g_labS[i];
    float Sown = 0.f, b = FLT_MAX;
#pragma unroll 1
    for (int c = 0; c < NCLUST; c++) {
        float s0 = 0.f, s1 = 0.f, s2 = 0.f, s3 = 0.f;
#pragma unroll
        for (int p = 0; p < NTILES; p += 4) {
            s0 += g_Spart[(size_t)((p + 0) * NCLUST + c) * N_SAMPLES + i];
            s1 += g_Spart[(size_t)((p + 1) * NCLUST + c) * N_SAMPLES + i];
            s2 += g_Spart[(size_t)((p + 2) * NCLUST + c) * N_SAMPLES + i];
            s3 += g_Spart[(size_t)((p + 3) * NCLUST + c) * N_SAMPLES + i];
        }
        float s = (s0 + s1) + (s2 + s3);
        int cnt = scounts[c];
        if (c == own) Sown = s;
        else if (cnt > 0) b = fminf(b, s / (float)cnt);
    }
    const int ocnt = scounts[own];
    const float a = Sown / fmaxf((float)ocnt - 1.f, 1.f);
    float score = 0.f;
    if (ocnt > 1) score = (b - a) / fmaxf(b, a);

    __shared__ float red[256];
    red[threadIdx.x] = score;
    __syncthreads();
    for (int s = 128; s > 0; s >>= 1) {
        if (threadIdx.x < s) red[threadIdx.x] += red[threadIdx.x + s];
        __syncthreads();
    }
    if (threadIdx.x == 0) g_partial[blockIdx.x] = red[0];
}

__global__ void final_kernel(float* out) {
    if (threadIdx.x == 0) {
        float s = 0.f;
#pragma unroll
        for (int b = 0; b < 32; b++) s += g_partial[b];
        out[0] = s / (float)N_SAMPLES;
    }
}

// ---------------------------------------------------------------------------
extern "C" void kernel_launch(void* const* d_in, const int* in_sizes, int n_in,
                              void* d_out, int out_size) {
    const float* F = (const float*)d_in[0];
    const int* Lraw = (const int*)d_in[1];
    float* out = (float*)d_out;

    const int smem_bytes = SMEM_FLOATS * 4;   // ~97 KB -> 2 CTAs/SM
    cudaFuncSetAttribute(dist_kernel,
                         cudaFuncAttributeMaxDynamicSharedMemorySize, smem_bytes);

    conv_labels_kernel<<<1, 256>>>(Lraw);
    sort_kernel<<<1, 256>>>();
    gatherT_kernel<<<N_SAMPLES / 32, 256>>>(F);
    dist_kernel<<<NPAIRS, 256, smem_bytes>>>();
    score_kernel<<<N_SAMPLES / 256, 256>>>();
    final_kernel<<<1, 32>>>(out);
}

// round 11
// speedup vs baseline: 1.3210x; 1.3210x over previous
#include <cuda_runtime.h>
#include <math.h>
#include <float.h>
#include <stdint.h>

#define N_SAMPLES 8192
#define DIM 128
#define NCLUST 64
#define TILE 128
#define NTILES (N_SAMPLES / TILE)   // 64
#define NPAIRS (NTILES * (NTILES + 1) / 2)   // 2080
#define KS 8                        // k-slab size
#define NSLAB (DIM / KS)            // 16
#define SPAD 65

// smem offsets in floats
// A slabs hold duplicated pairs: KS*TILE ull = 2048 floats (8KB) each
// B slabs: KS*TILE floats = 1024 floats (4KB) each
#define AS0 0
#define AS1 2048
#define BS0 4096
#define BS1 5120
#define SACCI 6144
#define SACCJ (SACCI + TILE * SPAD)
#define SMEM_FLOATS (SACCJ + TILE * SPAD)   // 22784 floats = 91.1KB

// ---- device scratch ----
typedef unsigned long long ull;
__device__ int   g_lab[N_SAMPLES];
__device__ int   g_labS[N_SAMPLES];
__device__ int   g_perm[N_SAMPLES];
__device__ float g_sqS[N_SAMPLES];
__device__ float g_FpT[DIM * N_SAMPLES];    // sorted, k-major
__device__ ull   g_FpTd[DIM * N_SAMPLES];   // sorted, k-major, duplicated pairs
__device__ int   g_counts[NCLUST];
__device__ float g_Spart[NTILES * NCLUST * N_SAMPLES];
__device__ float g_S[NCLUST * N_SAMPLES];
__device__ float g_partial[32];

__device__ __forceinline__ void fma2(ull& acc, ull a, ull b) {
    asm("fma.rn.f32x2 %0, %1, %2, %0;" : "+l"(acc) : "l"(a), "l"(b));
}
__device__ __forceinline__ ull dup2(float a) {
    ull r;
    asm("mov.b64 %0, {%1, %1};" : "=l"(r) : "f"(a));
    return r;
}
__device__ __forceinline__ uint32_t smem_u32(const void* p) {
    uint32_t a;
    asm("{ .reg .u64 t; cvta.to.shared.u64 t, %1; cvt.u32.u64 %0, t; }"
        : "=r"(a) : "l"(p));
    return a;
}
__device__ __forceinline__ void cp16(uint32_t dst, const void* src) {
    asm volatile("cp.async.cg.shared.global [%0], [%1], 16;"
                 :: "r"(dst), "l"(src) : "memory");
}
#define CP_COMMIT() asm volatile("cp.async.commit_group;" ::: "memory")
#define CP_WAIT1()  asm volatile("cp.async.wait_group 1;" ::: "memory")
#define CP_WAIT0()  asm volatile("cp.async.wait_group 0;" ::: "memory")

// ---------------------------------------------------------------------------
__global__ void conv_labels_kernel(const int* __restrict__ Lraw) {
    __shared__ int is64;
    if (threadIdx.x == 0) {
        int odd_or = 0, even_bad = 0;
        for (int k = 0; k < 256; k += 2) {
            odd_or   |= Lraw[k + 1];
            even_bad |= ((unsigned)Lraw[k] >= NCLUST);
        }
        is64 = (odd_or == 0 && !even_bad) ? 1 : 0;
    }
    __syncthreads();
    const int w = is64;
    for (int i = threadIdx.x; i < N_SAMPLES; i += blockDim.x) {
        int v = w ? Lraw[2 * i] : Lraw[i];
        g_lab[i] = min(max(v, 0), NCLUST - 1);
    }
}

// Deterministic counting sort by label: 256 segments x 32 elements.
__global__ void sort_kernel() {
    __shared__ unsigned short T[256][NCLUST];
    __shared__ int colTot[NCLUST];
    __shared__ int cbase[NCLUST];
    const int s = threadIdx.x;
#pragma unroll
    for (int c = 0; c < NCLUST; c++) T[s][c] = 0;
    const int e0 = s * 32;
    for (int e = 0; e < 32; e++) T[s][g_lab[e0 + e]]++;
    __syncthreads();
    if (s < NCLUST) {
        int tot = 0;
        for (int q = 0; q < 256; q++) tot += T[q][s];
        colTot[s] = tot;
        g_counts[s] = tot;
    }
    __syncthreads();
    if (s == 0) {
        int run = 0;
        for (int c = 0; c < NCLUST; c++) { cbase[c] = run; run += colTot[c]; }
    }
    __syncthreads();
    if (s < NCLUST) {
        int run = cbase[s];
        for (int q = 0; q < 256; q++) {
            int w = T[q][s];
            T[q][s] = (unsigned short)run;
            run += w;
        }
    }
    __syncthreads();
    for (int e = 0; e < 32; e++) {
        int idx = e0 + e;
        int c = g_lab[idx];
        int p = T[s][c]++;
        g_perm[p] = idx;
        g_labS[p] = c;
    }
}

// Gather (via perm) + transpose (plain + duplicated) + sq norms, fused.
__global__ void gatherT_kernel(const float* __restrict__ F) {
    __shared__ float T[32][DIM + 1];
    const int tid = threadIdx.x;
    const int lane = tid & 31, w = tid >> 5;
    const int base = blockIdx.x * 32;

#pragma unroll
    for (int rr = 0; rr < 4; rr++) {
        const int p = base + w * 4 + rr;
        const int src = g_perm[p];
        float4 v = reinterpret_cast<const float4*>(F)[src * 32 + lane];
        T[w * 4 + rr][lane * 4 + 0] = v.x;
        T[w * 4 + rr][lane * 4 + 1] = v.y;
        T[w * 4 + rr][lane * 4 + 2] = v.z;
        T[w * 4 + rr][lane * 4 + 3] = v.w;
        float s = v.x * v.x + v.y * v.y + v.z * v.z + v.w * v.w;
#pragma unroll
        for (int o = 16; o > 0; o >>= 1) s += __shfl_down_sync(0xffffffffu, s, o);
        if (lane == 0) g_sqS[p] = s;
    }
    __syncthreads();

    const int i = tid & 31, ksub = tid >> 5;
#pragma unroll
    for (int step = 0; step < 16; step++) {
        int k = step * 8 + ksub;
        float v = T[i][k];
        g_FpT[(size_t)k * N_SAMPLES + base + i] = v;
        g_FpTd[(size_t)k * N_SAMPLES + base + i] = dup2(v);
    }
}

// ---------------------------------------------------------------------------
// dist: one 128x128 tile per CTA, triangular grid. 8x8 reg tiling, FFMA2 with
// pre-duplicated A operands (no MOV dup chain), cp.async double-buffered slabs.
__global__ __launch_bounds__(256, 2) void dist_kernel() {
    int it = 0, rem = blockIdx.x, cnt = NTILES;
    while (rem >= cnt) { rem -= cnt; cnt--; it++; }
    const int jt = it + rem;
    const bool diag = (it == jt);

    extern __shared__ __align__(16) float smem[];
    const uint32_t sb = smem_u32(smem);
    const int tid = threadIdx.x;
    const int tx = tid & 15, ty = tid >> 4;
    const int iBase = it * TILE;
    const int jBase = jt * TILE;

    for (int t = tid; t < 2 * TILE * SPAD; t += 256) smem[SACCI + t] = 0.f;

    // A: 8 k-rows x 1024B (dup pairs) = 512 chunks; B: 8 x 512B = 256 chunks
#define ISSUE_SLAB(u)                                                         \
    {                                                                         \
        const int _b = (u) & 1;                                               \
        const ull* srcA = g_FpTd + (size_t)((u) * KS) * N_SAMPLES + iBase;    \
        const float* srcB = g_FpT + (size_t)((u) * KS) * N_SAMPLES + jBase;   \
        const uint32_t dA = sb + (_b ? AS1 : AS0) * 4;                        \
        const uint32_t dB = sb + (_b ? BS1 : BS0) * 4;                        \
        _Pragma("unroll")                                                     \
        for (int rr = 0; rr < 2; rr++) {                                      \
            int c = tid + rr * 256;                                           \
            int kk = c >> 6, off = (c & 63) * 2;                              \
            cp16(dA + (uint32_t)(kk * 1024 + (c & 63) * 16),                  \
                 srcA + (size_t)kk * N_SAMPLES + off);                        \
        }                                                                     \
        {                                                                     \
            int kk = tid >> 5, off = (tid & 31) * 4;                          \
            cp16(dB + (uint32_t)(kk * TILE + off) * 4,                        \
                 srcB + (size_t)kk * N_SAMPLES + off);                        \
        }                                                                     \
        CP_COMMIT();                                                          \
    }

    float isq[8];
#pragma unroll
    for (int ii = 0; ii < 8; ii++) isq[ii] = g_sqS[iBase + ty * 8 + ii];

    ull acc[32];
#pragma unroll
    for (int z = 0; z < 32; z++) acc[z] = 0ull;

    ISSUE_SLAB(0);
    ISSUE_SLAB(1);
    CP_WAIT1();
    __syncthreads();

#pragma unroll 1
    for (int u = 0; u < NSLAB; u++) {
        const int p = u & 1;
        const ull* Ab = reinterpret_cast<const ull*>(smem + (p ? AS1 : AS0)) + ty * 8;
        const float* bp = smem + (p ? BS1 : BS0) + tx * 8;

        ull b0C, b1C, b2C, b3C;
        asm("ld.shared.v2.u64 {%0, %1}, [%2];" : "=l"(b0C), "=l"(b1C) : "l"(bp));
        asm("ld.shared.v2.u64 {%0, %1}, [%2];" : "=l"(b2C), "=l"(b3C) : "l"(bp + 4));

#pragma unroll
        for (int k = 0; k < KS; k++) {
            const ull* ak = Ab + k * TILE;
            ull a0, a1, a2, a3, a4, a5, a6, a7;
            asm("ld.shared.v2.u64 {%0, %1}, [%2];" : "=l"(a0), "=l"(a1) : "l"(ak));
            asm("ld.shared.v2.u64 {%0, %1}, [%2];" : "=l"(a2), "=l"(a3) : "l"(ak + 2));
            asm("ld.shared.v2.u64 {%0, %1}, [%2];" : "=l"(a4), "=l"(a5) : "l"(ak + 4));
            asm("ld.shared.v2.u64 {%0, %1}, [%2];" : "=l"(a6), "=l"(a7) : "l"(ak + 6));
            ull b0N, b1N, b2N, b3N;
            if (k + 1 < KS) {
                asm("ld.shared.v2.u64 {%0, %1}, [%2];"
                    : "=l"(b0N), "=l"(b1N) : "l"(bp + (k + 1) * TILE));
                asm("ld.shared.v2.u64 {%0, %1}, [%2];"
                    : "=l"(b2N), "=l"(b3N) : "l"(bp + (k + 1) * TILE + 4));
            }
            fma2(acc[0],  a0, b0C); fma2(acc[1],  a0, b1C); fma2(acc[2],  a0, b2C); fma2(acc[3],  a0, b3C);
            fma2(acc[4],  a1, b0C); fma2(acc[5],  a1, b1C); fma2(acc[6],  a1, b2C); fma2(acc[7],  a1, b3C);
            fma2(acc[8],  a2, b0C); fma2(acc[9],  a2, b1C); fma2(acc[10], a2, b2C); fma2(acc[11], a2, b3C);
            fma2(acc[12], a3, b0C); fma2(acc[13], a3, b1C); fma2(acc[14], a3, b2C); fma2(acc[15], a3, b3C);
            fma2(acc[16], a4, b0C); fma2(acc[17], a4, b1C); fma2(acc[18], a4, b2C); fma2(acc[19], a4, b3C);
            fma2(acc[20], a5, b0C); fma2(acc[21], a5, b1C); fma2(acc[22], a5, b2C); fma2(acc[23], a5, b3C);
            fma2(acc[24], a6, b0C); fma2(acc[25], a6, b1C); fma2(acc[26], a6, b2C); fma2(acc[27], a6, b3C);
            fma2(acc[28], a7, b0C); fma2(acc[29], a7, b1C); fma2(acc[30], a7, b2C); fma2(acc[31], a7, b3C);
            b0C = b0N; b1C = b1N; b2C = b2N; b3C = b3N;
        }
        __syncthreads();
        if (u + 2 < NSLAB) {
            ISSUE_SLAB(u + 2);
            CP_WAIT1();
        } else {
            CP_WAIT0();
        }
        __syncthreads();
    }
#undef ISSUE_SLAB

    // ---- epilogue ----
    const int jbase = tx * 8;
    int   jlr[8], ilr[8];
    float jsr[8];
#pragma unroll
    for (int jj = 0; jj < 8; jj++) {
        jlr[jj] = g_labS[jBase + jbase + jj];
        jsr[jj] = g_sqS[jBase + jbase + jj];
        ilr[jj] = g_labS[iBase + ty * 8 + jj];
    }

#pragma unroll
    for (int q = 0; q < 32; q++) {
        const int ii = q >> 2, jp = q & 3;
        ull a2 = acc[q];
        float lo = __uint_as_float((unsigned)(a2 & 0xffffffffull));
        float hi = __uint_as_float((unsigned)(a2 >> 32));
        float d2lo = isq[ii] + jsr[2 * jp]     - 2.f * lo;
        float d2hi = isq[ii] + jsr[2 * jp + 1] - 2.f * hi;
        float dlo = 0.f, dhi = 0.f;
        const int gi = iBase + ty * 8 + ii;
        if (d2lo > 0.f && gi != (jBase + jbase + 2 * jp))
            asm("sqrt.approx.f32 %0, %1;" : "=f"(dlo) : "f"(d2lo));
        if (d2hi > 0.f && gi != (jBase + jbase + 2 * jp + 1))
            asm("sqrt.approx.f32 %0, %1;" : "=f"(dhi) : "f"(d2hi));
        asm("mov.b64 %0, {%1, %2};" : "=l"(acc[q]) : "f"(dlo), "f"(dhi));
    }

    float* SaccI = smem + SACCI;
    float* SaccJ = smem + SACCJ;

    // i-side: run-length over sorted j-labels
    {
        float run[8];
#pragma unroll
        for (int ii = 0; ii < 8; ii++) run[ii] = 0.f;
        int cur = jlr[0];
#pragma unroll
        for (int jj = 0; jj < 8; jj++) {
            const int c = jlr[jj];
            if (c != cur) {
#pragma unroll
                for (int ii = 0; ii < 8; ii++) {
                    atomicAdd(&SaccI[(ty * 8 + ii) * SPAD + cur], run[ii]);
                    run[ii] = 0.f;
                }
                cur = c;
            }
            const int jp = jj >> 1;
#pragma unroll
            for (int ii = 0; ii < 8; ii++) {
                ull a2 = acc[ii * 4 + jp];
                float d = (jj & 1) ? __uint_as_float((unsigned)(a2 >> 32))
                                   : __uint_as_float((unsigned)(a2 & 0xffffffffull));
                run[ii] += d;
            }
        }
#pragma unroll
        for (int ii = 0; ii < 8; ii++)
            atomicAdd(&SaccI[(ty * 8 + ii) * SPAD + cur], run[ii]);
    }

    // j-side (off-diag only): run-length over sorted i-labels
    if (!diag) {
        float run[8];
#pragma unroll
        for (int jj = 0; jj < 8; jj++) run[jj] = 0.f;
        int cur = ilr[0];
#pragma unroll
        for (int ii = 0; ii < 8; ii++) {
            const int c = ilr[ii];
            if (c != cur) {
#pragma unroll
                for (int jj = 0; jj < 8; jj++) {
                    atomicAdd(&SaccJ[(jbase + jj) * SPAD + cur], run[jj]);
                    run[jj] = 0.f;
                }
                cur = c;
            }
#pragma unroll
            for (int jj = 0; jj < 8; jj++) {
                ull a2 = acc[ii * 4 + (jj >> 1)];
                float d = (jj & 1) ? __uint_as_float((unsigned)(a2 >> 32))
                                   : __uint_as_float((unsigned)(a2 & 0xffffffffull));
                run[jj] += d;
            }
        }
#pragma unroll
        for (int jj = 0; jj < 8; jj++)
            atomicAdd(&SaccJ[(jbase + jj) * SPAD + cur], run[jj]);
    }
    __syncthreads();

    for (int idx = tid; idx < TILE * NCLUST; idx += 256) {
        int c = idx >> 7, il = idx & 127;
        g_Spart[(size_t)(jt * NCLUST + c) * N_SAMPLES + iBase + il] =
            SaccI[il * SPAD + c];
    }
    if (!diag) {
        for (int idx = tid; idx < TILE * NCLUST; idx += 256) {
            int c = idx >> 7, il = idx & 127;
            g_Spart[(size_t)(it * NCLUST + c) * N_SAMPLES + jBase + il] =
                SaccJ[il * SPAD + c];
        }
    }
}

// ---------------------------------------------------------------------------
// Streaming partner reduction (high occupancy) -> g_S[c][i]
__global__ void reduce_kernel() {
    const int t = blockIdx.x * 256 + threadIdx.x;
    float s0 = 0.f, s1 = 0.f, s2 = 0.f, s3 = 0.f;
#pragma unroll
    for (int p = 0; p < NTILES; p += 4) {
        s0 += g_Spart[(size_t)(p + 0) * NCLUST * N_SAMPLES + t];
        s1 += g_Spart[(size_t)(p + 1) * NCLUST * N_SAMPLES + t];
        s2 += g_Spart[(size_t)(p + 2) * NCLUST * N_SAMPLES + t];
        s3 += g_Spart[(size_t)(p + 3) * NCLUST * N_SAMPLES + t];
    }
    g_S[t] = (s0 + s1) + (s2 + s3);
}

__global__ void score_kernel() {
    const int i = blockIdx.x * 256 + threadIdx.x;
    __shared__ int scounts[NCLUST];
    if (threadIdx.x < NCLUST) scounts[threadIdx.x] = g_counts[threadIdx.x];
    __syncthreads();

    const int own = g_labS[i];
    float Sown = 0.f, b = FLT_MAX;
#pragma unroll
    for (int c = 0; c < NCLUST; c++) {
        float s = g_S[(size_t)c * N_SAMPLES + i];
        int cnt = scounts[c];
        if (c == own) Sown = s;
        else if (cnt > 0) b = fminf(b, s / (float)cnt);
    }
    const int ocnt = scounts[own];
    const float a = Sown / fmaxf((float)ocnt - 1.f, 1.f);
    float score = 0.f;
    if (ocnt > 1) score = (b - a) / fmaxf(b, a);

    __shared__ float red[256];
    red[threadIdx.x] = score;
    __syncthreads();
    for (int s = 128; s > 0; s >>= 1) {
        if (threadIdx.x < s) red[threadIdx.x] += red[threadIdx.x + s];
        __syncthreads();
    }
    if (threadIdx.x == 0) g_partial[blockIdx.x] = red[0];
}

__global__ void final_kernel(float* out) {
    if (threadIdx.x == 0) {
        float s = 0.f;
#pragma unroll
        for (int b = 0; b < 32; b++) s += g_partial[b];
        out[0] = s / (float)N_SAMPLES;
    }
}

// ---------------------------------------------------------------------------
extern "C" void kernel_launch(void* const* d_in, const int* in_sizes, int n_in,
                              void* d_out, int out_size) {
    const float* F = (const float*)d_in[0];
    const int* Lraw = (const int*)d_in[1];
    float* out = (float*)d_out;

    const int smem_bytes = SMEM_FLOATS * 4;   // ~91 KB -> 2 CTAs/SM
    cudaFuncSetAttribute(dist_kernel,
                         cudaFuncAttributeMaxDynamicSharedMemorySize, smem_bytes);

    conv_labels_kernel<<<1, 256>>>(Lraw);
    sort_kernel<<<1, 256>>>();
    gatherT_kernel<<<N_SAMPLES / 32, 256>>>(F);
    dist_kernel<<<NPAIRS, 256, smem_bytes>>>();
    reduce_kernel<<<NCLUST * N_SAMPLES / 256, 256>>>();
    score_kernel<<<N_SAMPLES / 256, 256>>>();
    final_kernel<<<1, 32>>>(out);
}

// round 12
// speedup vs baseline: 1.7925x; 1.3570x over previous
#include <cuda_runtime.h>
#include <math.h>
#include <float.h>
#include <stdint.h>

#define N_SAMPLES 8192
#define DIM 128
#define NCLUST 64
#define TILE_I 128
#define TILE_J 64
#define NTI (N_SAMPLES / TILE_I)    // 64
#define NTJ (N_SAMPLES / TILE_J)    // 128
#define NPAIRS 4160                 // sum_{it}(128-2it)
#define KS 16
#define NSLAB (DIM / KS)            // 8

// smem (floats): A slabs 16x128=2048 each, B slabs 16x64=1024 each
#define AS0 0
#define AS1 2048
#define BS0 4096
#define BS1 5120
#define SMEM_FLOATS 6144            // 24KB -> 3 CTAs/SM

typedef unsigned long long ull;
__device__ int   g_lab[N_SAMPLES];
__device__ int   g_labS[N_SAMPLES];
__device__ int   g_perm[N_SAMPLES];
__device__ float g_sqS[N_SAMPLES];
__device__ float g_FpT[DIM * N_SAMPLES];    // sorted, k-major
__device__ int   g_counts[NCLUST];
__device__ float g_S[NCLUST * N_SAMPLES];
__device__ float g_partial[32];

__device__ __forceinline__ void fma2(ull& acc, ull a, ull b) {
    asm("fma.rn.f32x2 %0, %1, %2, %0;" : "+l"(acc) : "l"(a), "l"(b));
}
__device__ __forceinline__ ull dup2(float a) {
    ull r;
    asm("mov.b64 %0, {%1, %1};" : "=l"(r) : "f"(a));
    return r;
}
__device__ __forceinline__ uint32_t smem_u32(const void* p) {
    uint32_t a;
    asm("{ .reg .u64 t; cvta.to.shared.u64 t, %1; cvt.u32.u64 %0, t; }"
        : "=r"(a) : "l"(p));
    return a;
}
__device__ __forceinline__ void cp16(uint32_t dst, const void* src) {
    asm volatile("cp.async.cg.shared.global [%0], [%1], 16;"
                 :: "r"(dst), "l"(src) : "memory");
}
#define CP_COMMIT() asm volatile("cp.async.commit_group;" ::: "memory")
#define CP_WAIT1()  asm volatile("cp.async.wait_group 1;" ::: "memory")
#define CP_WAIT0()  asm volatile("cp.async.wait_group 0;" ::: "memory")

// ---------------------------------------------------------------------------
__global__ void conv_labels_kernel(const int* __restrict__ Lraw) {
    __shared__ int is64;
    if (threadIdx.x == 0) {
        int odd_or = 0, even_bad = 0;
        for (int k = 0; k < 256; k += 2) {
            odd_or   |= Lraw[k + 1];
            even_bad |= ((unsigned)Lraw[k] >= NCLUST);
        }
        is64 = (odd_or == 0 && !even_bad) ? 1 : 0;
    }
    __syncthreads();
    const int w = is64;
    for (int i = threadIdx.x; i < N_SAMPLES; i += blockDim.x) {
        int v = w ? Lraw[2 * i] : Lraw[i];
        g_lab[i] = min(max(v, 0), NCLUST - 1);
    }
}

__global__ void sort_kernel() {
    __shared__ unsigned short T[256][NCLUST];
    __shared__ int colTot[NCLUST];
    __shared__ int cbase[NCLUST];
    const int s = threadIdx.x;
#pragma unroll
    for (int c = 0; c < NCLUST; c++) T[s][c] = 0;
    const int e0 = s * 32;
    for (int e = 0; e < 32; e++) T[s][g_lab[e0 + e]]++;
    __syncthreads();
    if (s < NCLUST) {
        int tot = 0;
        for (int q = 0; q < 256; q++) tot += T[q][s];
        colTot[s] = tot;
        g_counts[s] = tot;
    }
    __syncthreads();
    if (s == 0) {
        int run = 0;
        for (int c = 0; c < NCLUST; c++) { cbase[c] = run; run += colTot[c]; }
    }
    __syncthreads();
    if (s < NCLUST) {
        int run = cbase[s];
        for (int q = 0; q < 256; q++) {
            int w = T[q][s];
            T[q][s] = (unsigned short)run;
            run += w;
        }
    }
    __syncthreads();
    for (int e = 0; e < 32; e++) {
        int idx = e0 + e;
        int c = g_lab[idx];
        int p = T[s][c]++;
        g_perm[p] = idx;
        g_labS[p] = c;
    }
}

__global__ void gatherT_kernel(const float* __restrict__ F) {
    __shared__ float T[32][DIM + 1];
    const int tid = threadIdx.x;
    const int lane = tid & 31, w = tid >> 5;
    const int base = blockIdx.x * 32;
#pragma unroll
    for (int rr = 0; rr < 4; rr++) {
        const int p = base + w * 4 + rr;
        const int src = g_perm[p];
        float4 v = reinterpret_cast<const float4*>(F)[src * 32 + lane];
        T[w * 4 + rr][lane * 4 + 0] = v.x;
        T[w * 4 + rr][lane * 4 + 1] = v.y;
        T[w * 4 + rr][lane * 4 + 2] = v.z;
        T[w * 4 + rr][lane * 4 + 3] = v.w;
        float s = v.x * v.x + v.y * v.y + v.z * v.z + v.w * v.w;
#pragma unroll
        for (int o = 16; o > 0; o >>= 1) s += __shfl_down_sync(0xffffffffu, s, o);
        if (lane == 0) g_sqS[p] = s;
    }
    __syncthreads();
    const int i = tid & 31, ksub = tid >> 5;
#pragma unroll
    for (int step = 0; step < 16; step++) {
        int k = step * 8 + ksub;
        g_FpT[(size_t)k * N_SAMPLES + base + i] = T[i][k];
    }
}

__global__ void zeroS_kernel() {
    g_S[blockIdx.x * 1024 + threadIdx.x] = 0.f;
}

// ---------------------------------------------------------------------------
// dist: 128x64 half-tile per CTA, jh >= 2*it. 8x4 reg tiles, FFMA2,
// cp.async double-buffered slabs, epilogue accumulates straight into g_S
// via global atomics (L2-resident, run-length compressed by sorted labels).
__global__ __launch_bounds__(256, 3) void dist_kernel() {
    int it = 0, rem = blockIdx.x, cnt = NTJ;
    while (rem >= cnt) { rem -= cnt; cnt -= 2; it++; }
    const int jh = 2 * it + rem;
    const bool diagLike = (rem < 2);

    extern __shared__ __align__(16) float smem[];
    const uint32_t sb = smem_u32(smem);
    const int tid = threadIdx.x;
    const int tx = tid & 15, ty = tid >> 4;
    const int iBase = it * TILE_I;
    const int jBase = jh * TILE_J;

#define ISSUE_SLAB(u)                                                         \
    {                                                                         \
        const int _b = (u) & 1;                                               \
        const float* srcA = g_FpT + (size_t)((u) * KS) * N_SAMPLES + iBase;   \
        const float* srcB = g_FpT + (size_t)((u) * KS) * N_SAMPLES + jBase;   \
        const uint32_t dA = sb + (_b ? AS1 : AS0) * 4;                        \
        const uint32_t dB = sb + (_b ? BS1 : BS0) * 4;                        \
        _Pragma("unroll")                                                     \
        for (int rr = 0; rr < 2; rr++) {                                      \
            int c = tid + rr * 256;                                           \
            int kk = c >> 5, off = (c & 31) * 4;                              \
            cp16(dA + (uint32_t)(kk * TILE_I + off) * 4,                      \
                 srcA + (size_t)kk * N_SAMPLES + off);                        \
        }                                                                     \
        {                                                                     \
            int kk = tid >> 4, off = (tid & 15) * 4;                          \
            cp16(dB + (uint32_t)(kk * TILE_J + off) * 4,                      \
                 srcB + (size_t)kk * N_SAMPLES + off);                        \
        }                                                                     \
        CP_COMMIT();                                                          \
    }

    ull acc[16];
#pragma unroll
    for (int z = 0; z < 16; z++) acc[z] = 0ull;

    ISSUE_SLAB(0);
    ISSUE_SLAB(1);
    CP_WAIT1();
    __syncthreads();

#pragma unroll 1
    for (int u = 0; u < NSLAB; u++) {
        const int p = u & 1;
        const float* Ab = smem + (p ? AS1 : AS0) + ty * 8;
        const float* bp = smem + (p ? BS1 : BS0) + tx * 4;

        float4 aLoC = *reinterpret_cast<const float4*>(Ab);
        float4 aHiC = *reinterpret_cast<const float4*>(Ab + 4);
        ull b0C, b1C;
        asm("ld.shared.v2.u64 {%0, %1}, [%2];" : "=l"(b0C), "=l"(b1C) : "l"(bp));

#pragma unroll
        for (int k = 0; k < KS; k++) {
            float4 aLoN, aHiN;
            ull b0N, b1N;
            if (k + 1 < KS) {
                aLoN = *reinterpret_cast<const float4*>(Ab + (k + 1) * TILE_I);
                aHiN = *reinterpret_cast<const float4*>(Ab + (k + 1) * TILE_I + 4);
                asm("ld.shared.v2.u64 {%0, %1}, [%2];"
                    : "=l"(b0N), "=l"(b1N) : "l"(bp + (k + 1) * TILE_J));
            }
            ull a;
            a = dup2(aLoC.x); fma2(acc[0],  a, b0C); fma2(acc[1],  a, b1C);
            a = dup2(aLoC.y); fma2(acc[2],  a, b0C); fma2(acc[3],  a, b1C);
            a = dup2(aLoC.z); fma2(acc[4],  a, b0C); fma2(acc[5],  a, b1C);
            a = dup2(aLoC.w); fma2(acc[6],  a, b0C); fma2(acc[7],  a, b1C);
            a = dup2(aHiC.x); fma2(acc[8],  a, b0C); fma2(acc[9],  a, b1C);
            a = dup2(aHiC.y); fma2(acc[10], a, b0C); fma2(acc[11], a, b1C);
            a = dup2(aHiC.z); fma2(acc[12], a, b0C); fma2(acc[13], a, b1C);
            a = dup2(aHiC.w); fma2(acc[14], a, b0C); fma2(acc[15], a, b1C);
            aLoC = aLoN; aHiC = aHiN;
            b0C = b0N; b1C = b1N;
        }
        __syncthreads();
        if (u + 2 < NSLAB) {
            ISSUE_SLAB(u + 2);
            CP_WAIT1();
        } else {
            CP_WAIT0();
        }
        __syncthreads();
    }
#undef ISSUE_SLAB

    // ---- epilogue: dots -> distances -> run-length atomics into g_S ----
    float isq[8];
    int   ilr[8];
#pragma unroll
    for (int ii = 0; ii < 8; ii++) {
        const int gi = iBase + ty * 8 + ii;
        isq[ii] = g_sqS[gi];
        ilr[ii] = g_labS[gi];
    }
    int   jlr[4];
    float jsr[4];
#pragma unroll
    for (int jj = 0; jj < 4; jj++) {
        const int gj = jBase + tx * 4 + jj;
        jlr[jj] = g_labS[gj];
        jsr[jj] = g_sqS[gj];
    }

#pragma unroll
    for (int q = 0; q < 16; q++) {
        const int ii = q >> 1, jp = q & 1;
        ull a2 = acc[q];
        float lo = __uint_as_float((unsigned)(a2 & 0xffffffffull));
        float hi = __uint_as_float((unsigned)(a2 >> 32));
        const int gi = iBase + ty * 8 + ii;
        const int gj = jBase + tx * 4 + jp * 2;
        float d2lo = isq[ii] + jsr[jp * 2]     - 2.f * lo;
        float d2hi = isq[ii] + jsr[jp * 2 + 1] - 2.f * hi;
        float dlo = 0.f, dhi = 0.f;
        if (d2lo > 0.f && gi != gj)
            asm("sqrt.approx.f32 %0, %1;" : "=f"(dlo) : "f"(d2lo));
        if (d2hi > 0.f && gi != gj + 1)
            asm("sqrt.approx.f32 %0, %1;" : "=f"(dhi) : "f"(d2hi));
        asm("mov.b64 %0, {%1, %2};" : "=l"(acc[q]) : "f"(dlo), "f"(dhi));
    }

    // i-side: rows gi get sum over j grouped by j-label
    {
        float run[8];
#pragma unroll
        for (int ii = 0; ii < 8; ii++) run[ii] = 0.f;
        int cur = jlr[0];
#pragma unroll
        for (int jj = 0; jj < 4; jj++) {
            const int c = jlr[jj];
            if (c != cur) {
#pragma unroll
                for (int ii = 0; ii < 8; ii++) {
                    atomicAdd(&g_S[(size_t)cur * N_SAMPLES + iBase + ty * 8 + ii],
                              run[ii]);
                    run[ii] = 0.f;
                }
                cur = c;
            }
            const int jp = jj >> 1;
#pragma unroll
            for (int ii = 0; ii < 8; ii++) {
                ull a2 = acc[ii * 2 + jp];
                float d = (jj & 1) ? __uint_as_float((unsigned)(a2 >> 32))
                                   : __uint_as_float((unsigned)(a2 & 0xffffffffull));
                run[ii] += d;
            }
        }
#pragma unroll
        for (int ii = 0; ii < 8; ii++)
            atomicAdd(&g_S[(size_t)cur * N_SAMPLES + iBase + ty * 8 + ii],
                      run[ii]);
    }

    // j-side (off-diag only): cols gj get sum over i grouped by i-label
    if (!diagLike) {
        float run[4];
#pragma unroll
        for (int jj = 0; jj < 4; jj++) run[jj] = 0.f;
        int cur = ilr[0];
#pragma unroll
        for (int ii = 0; ii < 8; ii++) {
            const int c = ilr[ii];
            if (c != cur) {
#pragma unroll
                for (int jj = 0; jj < 4; jj++) {
                    atomicAdd(&g_S[(size_t)cur * N_SAMPLES + jBase + tx * 4 + jj],
                              run[jj]);
                    run[jj] = 0.f;
                }
                cur = c;
            }
#pragma unroll
            for (int jj = 0; jj < 4; jj++) {
                ull a2 = acc[ii * 2 + (jj >> 1)];
                float d = (jj & 1) ? __uint_as_float((unsigned)(a2 >> 32))
                                   : __uint_as_float((unsigned)(a2 & 0xffffffffull));
                run[jj] += d;
            }
        }
#pragma unroll
        for (int jj = 0; jj < 4; jj++)
            atomicAdd(&g_S[(size_t)cur * N_SAMPLES + jBase + tx * 4 + jj],
                      run[jj]);
    }
}

// ---------------------------------------------------------------------------
__global__ void score_kernel() {
    const int i = blockIdx.x * 256 + threadIdx.x;
    __shared__ int scounts[NCLUST];
    if (threadIdx.x < NCLUST) scounts[threadIdx.x] = g_counts[threadIdx.x];
    __syncthreads();

    const int own = g_labS[i];
    float Sown = 0.f, b = FLT_MAX;
#pragma unroll
    for (int c = 0; c < NCLUST; c++) {
        float s = g_S[(size_t)c * N_SAMPLES + i];
        int cnt = scounts[c];
        if (c == own) Sown = s;
        else if (cnt > 0) b = fminf(b, s / (float)cnt);
    }
    const int ocnt = scounts[own];
    const float a = Sown / fmaxf((float)ocnt - 1.f, 1.f);
    float score = 0.f;
    if (ocnt > 1) score = (b - a) / fmaxf(b, a);

    __shared__ float red[256];
    red[threadIdx.x] = score;
    __syncthreads();
    for (int s = 128; s > 0; s >>= 1) {
        if (threadIdx.x < s) red[threadIdx.x] += red[threadIdx.x + s];
        __syncthreads();
    }
    if (threadIdx.x == 0) g_partial[blockIdx.x] = red[0];
}

__global__ void final_kernel(float* out) {
    if (threadIdx.x == 0) {
        float s = 0.f;
#pragma unroll
        for (int b = 0; b < 32; b++) s += g_partial[b];
        out[0] = s / (float)N_SAMPLES;
    }
}

// ---------------------------------------------------------------------------
extern "C" void kernel_launch(void* const* d_in, const int* in_sizes, int n_in,
                              void* d_out, int out_size) {
    const float* F = (const float*)d_in[0];
    const int* Lraw = (const int*)d_in[1];
    float* out = (float*)d_out;

    const int smem_bytes = SMEM_FLOATS * 4;   // 24KB -> 3 CTAs/SM
    cudaFuncSetAttribute(dist_kernel,
                         cudaFuncAttributeMaxDynamicSharedMemorySize, smem_bytes);

    conv_labels_kernel<<<1, 256>>>(Lraw);
    sort_kernel<<<1, 256>>>();
    gatherT_kernel<<<N_SAMPLES / 32, 256>>>(F);
    zeroS_kernel<<<NCLUST * N_SAMPLES / 1024, 1024>>>();
    dist_kernel<<<NPAIRS, 256, smem_bytes>>>();
    score_kernel<<<N_SAMPLES / 256, 256>>>();
    final_kernel<<<1, 32>>>(out);
}